// round 9
// baseline (speedup 1.0000x reference)
#include <cuda_runtime.h>
#include <cstdint>

// FisherLayer: N=8192, D=256, K=32. Single fused persistent kernel.
//   y4[n,k]   = -0.5*( sum_d a*x^2 + u*x + c_k ),  a=w^2, u=2w^2 b, c_k=sum a b^2
//               per-element: a*x^2 + u*x = x*(a*x + u)
//   S0[k], Sx[k,d]=sum_n g*x, Sx2[k,d]=sum_n g*x^2
//   out_mu    = w*(Sx + b*S0)/N
//   out_sigma = (w^2*(Sx2 + 2*b*Sx + b^2*S0) - S0)/(sqrt(2)*N)
// 512 thr/CTA, 16-row batches, params in smem -> ~100 regs -> 4 warps/SMSP.

#define NROWS 8192
#define DD    256
#define KK    32
#define GRID_MAIN 148
#define RPB   16
#define NB16  (NROWS / RPB)    // 512
#define THREADS 512

typedef unsigned long long u64;

// g_P[chunk 0..127][row 0..147][32 float4]; col = p*256+d; chunk=col>>5
// float4 = (Sx[2p,d], Sx[2p+1,d], Sx2[2p,d], Sx2[2p+1,d])
__device__ __align__(128) float4 g_P[128 * GRID_MAIN * 32];
__device__ float    g_PS0[GRID_MAIN * KK];
__device__ unsigned g_ctr = 0;   // monotonic across graph replays

__device__ __forceinline__ u64 pack2(float lo, float hi) {
    u64 r; asm("mov.b64 %0, {%1, %2};" : "=l"(r) : "f"(lo), "f"(hi)); return r;
}
__device__ __forceinline__ float2 unpack2(u64 v) {
    float2 f; asm("mov.b64 {%0, %1}, %2;" : "=f"(f.x), "=f"(f.y) : "l"(v)); return f;
}
__device__ __forceinline__ u64 fma2(u64 a, u64 b, u64 c) {
    u64 d; asm("fma.rn.f32x2 %0, %1, %2, %3;" : "=l"(d) : "l"(a), "l"(b), "l"(c)); return d;
}

// dynamic smem layout (bytes):
//   [0,      32768)  s_x   : 2 x 4096 floats (16 rows x 256), double buffer
//   [32768,  98304)  s_pp  : 4096 ulonglong2  (dpair 0..127, k 0..31) = (ap,up)
//   [98304, 114688)  s_part: 4096 floats  [slice 0..7][row 0..15][k 0..31]
//   [114688,116736)  s_gamma: 512 floats  [row][k]
//   [116736,118784)  s_cred : 512 floats
//   [118784,118792)  s_S0v  : 2 floats
#define SMEM_BYTES 118800

__global__ void __launch_bounds__(THREADS, 1) fisher_all(const float* __restrict__ x,
                                                         const float* __restrict__ w,
                                                         const float* __restrict__ b,
                                                         float* __restrict__ out) {
    extern __shared__ __align__(16) char smem[];
    float*      s_xf    = reinterpret_cast<float*>(smem);
    float4*     s_x4    = reinterpret_cast<float4*>(smem);
    ulonglong2* s_pp    = reinterpret_cast<ulonglong2*>(smem + 32768);
    float*      s_part  = reinterpret_cast<float*>(smem + 98304);
    float*      s_gamma = reinterpret_cast<float*>(smem + 114688);
    float*      s_cred  = reinterpret_cast<float*>(smem + 116736);
    float*      s_S0v   = reinterpret_cast<float*>(smem + 118784);

    const int tid  = threadIdx.x;
    const int wrp  = tid >> 5;    // 0..15
    const int lane = tid & 31;
    const int bid  = blockIdx.x;

    // prefetch first batch while params are built
    int batch = bid;
    float4 v0, v1;
    {
        const float4* xb = reinterpret_cast<const float4*>(x) + (size_t)batch * 1024;
        v0 = xb[tid]; v1 = xb[tid + 512];
    }

    // ---- build param table: (ap,up) per (dpair, k) ----
    #pragma unroll
    for (int i = 0; i < 8; i++) {
        int idx = tid + i * 512;           // idx = k*128 + dpair
        int k   = idx >> 7;
        int dp  = idx & 127;
        float2 wv = *reinterpret_cast<const float2*>(&w[k * DD + 2 * dp]);
        float2 bv = *reinterpret_cast<const float2*>(&b[k * DD + 2 * dp]);
        float a0 = wv.x * wv.x, a1 = wv.y * wv.y;
        ulonglong2 e;
        e.x = pack2(a0, a1);
        e.y = pack2(2.0f * a0 * bv.x, 2.0f * a1 * bv.y);
        s_pp[dp * 32 + k] = e;
    }
    // ---- c_k partials: thread (chunk = tid>>5, k = lane) over 16 d ----
    {
        int ch = wrp;   // 0..15
        float cp = 0.0f;
        const float* wr = w + lane * DD + ch * 16;
        const float* br = b + lane * DD + ch * 16;
        #pragma unroll
        for (int j = 0; j < 16; j++) {
            float a = wr[j] * wr[j];
            cp += a * br[j] * br[j];
        }
        s_cred[ch * 32 + lane] = cp;
    }
    __syncthreads();
    float c_reg = 0.0f;
    #pragma unroll
    for (int j = 0; j < 16; j++) c_reg += s_cred[j * 32 + lane];

    // phase-A role: slice s (32 d's), row-half rh (8 rows)
    const int sA  = wrp & 7;
    const int rhA = wrp >> 3;
    // phase-B role: d = tid&255, k-half kh = tid>>8 (16 k's)
    const int dB = tid & 255;
    const int kh = tid >> 8;

    u64 accx[8], accx2[8];
    #pragma unroll
    for (int p = 0; p < 8; p++) { accx[p] = 0ull; accx2[p] = 0ull; }
    float s0acc = 0.0f;

    int bufsel = 0;
    for (;;) {
        reinterpret_cast<float4*>(s_x4)[bufsel * 1024 + tid]       = v0;
        reinterpret_cast<float4*>(s_x4)[bufsel * 1024 + tid + 512] = v1;

        int nbatch = batch + GRID_MAIN;
        bool nhave = nbatch < NB16;
        if (nhave) {
            const float4* xb = reinterpret_cast<const float4*>(x) + (size_t)nbatch * 1024;
            v0 = xb[tid]; v1 = xb[tid + 512];
        }
        __syncthreads();

        const ulonglong2* bx =
            reinterpret_cast<const ulonglong2*>(s_xf + bufsel * 4096);

        // ---- phase A: 8 rows x 32 d per warp, params from smem ----
        {
            u64 accA[8];
            #pragma unroll
            for (int r = 0; r < 8; r++) accA[r] = 0ull;
            #pragma unroll
            for (int q = 0; q < 8; q++) {
                ulonglong2 pq0 = s_pp[(sA * 16 + 2 * q)     * 32 + lane];
                ulonglong2 pq1 = s_pp[(sA * 16 + 2 * q + 1) * 32 + lane];
                #pragma unroll
                for (int r = 0; r < 8; r++) {
                    ulonglong2 v = bx[(rhA * 8 + r) * 64 + sA * 8 + q];
                    accA[r] = fma2(v.x, fma2(pq0.x, v.x, pq0.y), accA[r]);
                    accA[r] = fma2(v.y, fma2(pq1.x, v.y, pq1.y), accA[r]);
                }
            }
            #pragma unroll
            for (int r = 0; r < 8; r++) {
                float2 p = unpack2(accA[r]);
                s_part[sA * 512 + (rhA * 8 + r) * 32 + lane] = p.x + p.y;
            }
        }
        __syncthreads();

        // ---- softmax: warp wrp owns row wrp (16 rows), lane = k ----
        {
            float y = 0.0f;
            #pragma unroll
            for (int j = 0; j < 8; j++) y += s_part[j * 512 + wrp * 32 + lane];
            y = -0.5f * (y + c_reg);
            float m = y;
            #pragma unroll
            for (int o = 16; o; o >>= 1) m = fmaxf(m, __shfl_xor_sync(0xffffffffu, m, o));
            float e = __expf(y - m);
            float s = e;
            #pragma unroll
            for (int o = 16; o; o >>= 1) s += __shfl_xor_sync(0xffffffffu, s, o);
            float g = e / s;
            s0acc += g;
            s_gamma[wrp * 32 + lane] = g;
        }
        __syncthreads();

        // ---- phase B: thread owns 1 d x 16 k, 16 rows ----
        {
            const float* xb = s_xf + bufsel * 4096;
            #pragma unroll
            for (int r = 0; r < RPB; r++) {
                float xv = xb[r * 256 + dB];
                u64 px  = pack2(xv, xv);
                float sq = xv * xv;
                u64 px2 = pack2(sq, sq);
                const ulonglong2* grow =
                    reinterpret_cast<const ulonglong2*>(&s_gamma[r * 32 + kh * 16]);
                #pragma unroll
                for (int t = 0; t < 4; t++) {
                    ulonglong2 gg = grow[t];
                    accx [2 * t]     = fma2(gg.x, px,  accx [2 * t]);
                    accx2[2 * t]     = fma2(gg.x, px2, accx2[2 * t]);
                    accx [2 * t + 1] = fma2(gg.y, px,  accx [2 * t + 1]);
                    accx2[2 * t + 1] = fma2(gg.y, px2, accx2[2 * t + 1]);
                }
            }
        }

        if (!nhave) break;
        batch = nbatch;
        bufsel ^= 1;
    }

    // ---- S0 per-block combine ----
    __syncthreads();
    s_cred[wrp * 32 + lane] = s0acc;
    __syncthreads();
    if (wrp == 0) {
        float v = 0.0f;
        #pragma unroll
        for (int j = 0; j < 16; j++) v += s_cred[j * 32 + lane];
        g_PS0[bid * KK + lane] = v;
    }

    // ---- write partials: chunk-major, coalesced ----
    {
        ulonglong2* pg = reinterpret_cast<ulonglong2*>(g_P);
        #pragma unroll
        for (int t = 0; t < 8; t++) {
            int p = kh * 8 + t;
            int chunk = p * 8 + (dB >> 5);
            size_t idx = ((size_t)chunk * GRID_MAIN + bid) * 32 + (dB & 31);
            ulonglong2 v; v.x = accx[t]; v.y = accx2[t];
            pg[idx] = v;
        }
    }

    // ---- grid-wide barrier (148 CTAs, 1/SM) ----
    __threadfence();
    __syncthreads();
    if (bid >= 128) {
        if (tid == 0) atomicAdd(&g_ctr, 1u);
        return;
    }
    if (tid == 0) {
        unsigned my = atomicAdd(&g_ctr, 1u);
        unsigned target = my - (my % (unsigned)GRID_MAIN) + (unsigned)GRID_MAIN;
        while (*(volatile unsigned*)&g_ctr < target) { }
    }
    __syncthreads();
    __threadfence();

    // ---- fused reduction + finalize: blocks 0..127, one chunk each ----
    const int cb = bid;
    const float4* src = g_P + (size_t)cb * GRID_MAIN * 32;
    float4* s_red4 = reinterpret_cast<float4*>(s_part);   // 16KB reuse
    const int q4 = tid & 31;
    const int rg = tid >> 5;      // 16 row-groups
    float4 a = make_float4(0.f, 0.f, 0.f, 0.f);
    #pragma unroll 2
    for (int r = rg; r < GRID_MAIN; r += 16) {
        float4 v = src[r * 32 + q4];
        a.x += v.x; a.y += v.y; a.z += v.z; a.w += v.w;
    }
    s_red4[rg * 32 + q4] = a;

    if (wrp == 1) {   // S0 for this chunk's two k's
        int ks = lane >> 4;
        int j  = lane & 15;
        int p  = cb >> 3;
        float s = 0.0f;
        for (int bb = j; bb < GRID_MAIN; bb += 16) s += g_PS0[bb * KK + 2 * p + ks];
        #pragma unroll
        for (int o = 1; o < 16; o <<= 1) s += __shfl_xor_sync(0xffffffffu, s, o);
        if (j == 0) s_S0v[ks] = s;
    }
    __syncthreads();

    if (tid < 32) {
        float4 tot = make_float4(0.f, 0.f, 0.f, 0.f);
        #pragma unroll
        for (int gq = 0; gq < 16; gq++) {
            float4 v = s_red4[gq * 32 + tid];
            tot.x += v.x; tot.y += v.y; tot.z += v.z; tot.w += v.w;
        }
        const int p  = cb >> 3;
        const int d  = (cb & 7) * 32 + tid;
        const int k0 = 2 * p, k1 = 2 * p + 1;
        const float invN   = 1.0f / (float)NROWS;
        const float invNs2 = invN * 0.70710678118654752440f;

        {
            float wv = w[k0 * DD + d], bv = b[k0 * DD + d], S0 = s_S0v[0];
            float mu  = wv * (tot.x + bv * S0) * invN;
            float Ey2 = wv * wv * (tot.z + 2.0f * bv * tot.x + bv * bv * S0);
            out[k0 * DD + d]           = (Ey2 - S0) * invNs2;
            out[KK * DD + k0 * DD + d] = mu;
        }
        {
            float wv = w[k1 * DD + d], bv = b[k1 * DD + d], S0 = s_S0v[1];
            float mu  = wv * (tot.y + bv * S0) * invN;
            float Ey2 = wv * wv * (tot.w + 2.0f * bv * tot.y + bv * bv * S0);
            out[k1 * DD + d]           = (Ey2 - S0) * invNs2;
            out[KK * DD + k1 * DD + d] = mu;
        }
    }
}

extern "C" void kernel_launch(void* const* d_in, const int* in_sizes, int n_in,
                              void* d_out, int out_size) {
    const float* x = (const float*)d_in[0];
    const float* w = (const float*)d_in[1];
    const float* b = (const float*)d_in[2];
    float* out = (float*)d_out;
    (void)in_sizes; (void)n_in; (void)out_size;

    cudaFuncSetAttribute(fisher_all, cudaFuncAttributeMaxDynamicSharedMemorySize,
                         SMEM_BYTES);
    fisher_all<<<GRID_MAIN, THREADS, SMEM_BYTES>>>(x, w, b, out);
}